// round 2
// baseline (speedup 1.0000x reference)
#include <cuda_runtime.h>
#include <cstdint>

// Problem shape (fixed by the dataset)
#define NN  100000
#define OC  64
#define OC4 (OC / 4)   // 16 float4 per row

// Scratch: W transposed to [N, 64] so each gathered column is one contiguous
// 256B row. Static __device__ array = allowed scratch (no allocations).
__device__ float g_Wt[(size_t)NN * OC];
__device__ int   g_is64;

// ---------------------------------------------------------------------------
// Kernel 0: detect edge_index dtype. int64 little-endian small non-negative
// values have zero high words; uniform int32 in [0,1e5) essentially never has
// 32 consecutive odd words all zero.
// ---------------------------------------------------------------------------
__global__ void k_detect(const unsigned int* __restrict__ ei)
{
    int ok = 1;
#pragma unroll
    for (int k = 1; k < 64; k += 2)
        ok &= (ei[k] == 0u);
    g_is64 = ok;
}

// ---------------------------------------------------------------------------
// Kernel 1: transpose W [64, N] -> Wt [N, 64] via smem tiles
// ---------------------------------------------------------------------------
__global__ void k_transpose(const float* __restrict__ W, int n)
{
    __shared__ float s[32][OC + 1];
    const int j0 = blockIdx.x * 32;
    const int tx = threadIdx.x;       // 0..31
    const int ty = threadIdx.y;       // 0..7

    if (j0 + tx < n) {
#pragma unroll
        for (int o = ty; o < OC; o += 8)
            s[tx][o] = W[(size_t)o * n + j0 + tx];
    }
    __syncthreads();

#pragma unroll
    for (int jj = ty; jj < 32; jj += 8) {
        if (j0 + jj < n) {
            g_Wt[(size_t)(j0 + jj) * OC + tx]      = s[jj][tx];
            g_Wt[(size_t)(j0 + jj) * OC + tx + 32] = s[jj][tx + 32];
        }
    }
}

// ---------------------------------------------------------------------------
// Kernel 2: init output with the bias (output is poisoned before timing)
// ---------------------------------------------------------------------------
__global__ void k_init_bias(float* __restrict__ out, const float* __restrict__ b,
                            size_t total)
{
    size_t i = (size_t)blockIdx.x * blockDim.x + threadIdx.x;
    if (i < total)
        out[i] = __ldg(b + (i & (OC - 1)));
}

// ---------------------------------------------------------------------------
// Kernel 3: edge scatter. 16 lanes per edge; each lane moves one float4:
//   v = Wt[col][lane*4..+3];  out[row][lane*4..+3] += v  (red.global.v4)
// ---------------------------------------------------------------------------
__global__ void k_edge_scatter(const void* __restrict__ ei_raw,
                               float4* __restrict__ out4,
                               long long E)
{
    long long t   = (long long)blockIdx.x * blockDim.x + threadIdx.x;
    long long eid = t >> 4;
    int       sub = (int)(t & 15);
    if (eid >= E) return;

    int row, col;
    if (g_is64) {
        const long long* e64 = (const long long*)ei_raw;
        row = (int)__ldg(e64 + eid);
        col = (int)__ldg(e64 + E + eid);
    } else {
        const int* e32 = (const int*)ei_raw;
        row = __ldg(e32 + eid);
        col = __ldg(e32 + E + eid);
    }
    if ((unsigned)row >= (unsigned)NN || (unsigned)col >= (unsigned)NN) return;

    const float4* Wt4 = (const float4*)g_Wt;
    float4 v = __ldg(Wt4 + (size_t)col * OC4 + sub);
    float4* p = out4 + (size_t)row * OC4 + sub;

    asm volatile("red.global.add.v4.f32 [%0], {%1, %2, %3, %4};"
                 :: "l"(p), "f"(v.x), "f"(v.y), "f"(v.z), "f"(v.w)
                 : "memory");
}

// ---------------------------------------------------------------------------
extern "C" void kernel_launch(void* const* d_in, const int* in_sizes, int n_in,
                              void* d_out, int out_size)
{
    const void*  ei  = d_in[0];                  // [2, E] int32 or int64
    const float* W   = (const float*)d_in[1];    // [64, N]
    const float* b   = (const float*)d_in[2];    // [64]
    float*       out = (float*)d_out;            // [N, 64]

    const long long E = (long long)in_sizes[0] / 2;
    const int       n = in_sizes[1] / OC;         // = NN

    // 0) dtype detection
    k_detect<<<1, 1>>>((const unsigned int*)ei);

    // 1) transpose W into g_Wt
    {
        dim3 blk(32, 8);
        dim3 grd((n + 31) / 32);
        k_transpose<<<grd, blk>>>(W, n);
    }

    // 2) out = broadcast bias
    {
        size_t total = (size_t)n * OC;
        int threads = 256;
        int blocks  = (int)((total + threads - 1) / threads);
        k_init_bias<<<blocks, threads>>>(out, b, total);
    }

    // 3) scatter-add all edges
    {
        long long total_threads = E * 16;
        int threads = 256;
        long long blocks = (total_threads + threads - 1) / threads;
        k_edge_scatter<<<(unsigned)blocks, threads>>>(ei, (float4*)out, E);
    }
}

// round 4
// speedup vs baseline: 1.3717x; 1.3717x over previous
#include <cuda_runtime.h>
#include <cstdint>

#define NN    100000
#define OC    64
#define OC4   (OC / 4)          // 16 float4 per row
#define SCAN_CHUNK 512
#define NCHUNK ((NN + 1 + SCAN_CHUNK - 1) / SCAN_CHUNK)   // 196

// ---- static scratch (no allocations allowed) -------------------------------
__device__ __align__(16) float g_Wt[(size_t)NN * OC];  // W transposed [N,64]
__device__ int  g_cols[3200000 + 64];                  // cols sorted by row
__device__ int  g_counts[NN + 1];
__device__ int  g_row_start[NN + 1];
__device__ int  g_cursor[NN];
__device__ int  g_chunk_sums[NCHUNK];
__device__ int  g_is64;

// ---------------------------------------------------------------------------
// dtype detect: int64 little-endian small values have zero odd words
// ---------------------------------------------------------------------------
__global__ void k_detect(const unsigned int* __restrict__ ei)
{
    int ok = 1;
#pragma unroll
    for (int k = 1; k < 64; k += 2) ok &= (ei[k] == 0u);
    g_is64 = ok;
}

__device__ __forceinline__ int load_idx(const void* ei, long long pos)
{
    if (g_is64) return (int)__ldg(((const long long*)ei) + pos);
    return __ldg(((const int*)ei) + pos);
}

// ---------------------------------------------------------------------------
// transpose W [64,N] -> g_Wt [N,64]
// ---------------------------------------------------------------------------
__global__ void k_transpose(const float* __restrict__ W, int n)
{
    __shared__ float s[32][OC + 1];
    const int j0 = blockIdx.x * 32;
    const int tx = threadIdx.x, ty = threadIdx.y;

    if (j0 + tx < n) {
#pragma unroll
        for (int o = ty; o < OC; o += 8)
            s[tx][o] = W[(size_t)o * n + j0 + tx];
    }
    __syncthreads();
#pragma unroll
    for (int jj = ty; jj < 32; jj += 8) {
        if (j0 + jj < n) {
            g_Wt[(size_t)(j0 + jj) * OC + tx]      = s[jj][tx];
            g_Wt[(size_t)(j0 + jj) * OC + tx + 32] = s[jj][tx + 32];
        }
    }
}

// ---------------------------------------------------------------------------
// counting sort: histogram -> exclusive scan -> scatter cols
// ---------------------------------------------------------------------------
__global__ void k_zero_counts()
{
    int i = blockIdx.x * blockDim.x + threadIdx.x;
    if (i <= NN) g_counts[i] = 0;
}

__global__ void k_hist(const void* __restrict__ ei, long long E)
{
    long long e = (long long)blockIdx.x * blockDim.x + threadIdx.x;
    if (e >= E) return;
    int row = load_idx(ei, e);
    if ((unsigned)row < (unsigned)NN) atomicAdd(&g_counts[row], 1);
}

// per-chunk exclusive scan (Hillis-Steele in smem)
__global__ void k_scan1()
{
    __shared__ int s[SCAN_CHUNK];
    int t = threadIdx.x;
    int g = blockIdx.x * SCAN_CHUNK + t;
    int v = (g <= NN) ? g_counts[g] : 0;
    s[t] = v;
    __syncthreads();
#pragma unroll
    for (int off = 1; off < SCAN_CHUNK; off <<= 1) {
        int add = (t >= off) ? s[t - off] : 0;
        __syncthreads();
        s[t] += add;
        __syncthreads();
    }
    if (g <= NN) g_row_start[g] = s[t] - v;           // exclusive
    if (t == SCAN_CHUNK - 1) g_chunk_sums[blockIdx.x] = s[t];
}

__global__ void k_scan2()
{
    int acc = 0;
    for (int c = 0; c < NCHUNK; ++c) {
        int v = g_chunk_sums[c];
        g_chunk_sums[c] = acc;
        acc += v;
    }
}

__global__ void k_scan3()
{
    int t = threadIdx.x;
    int g = blockIdx.x * SCAN_CHUNK + t;
    if (g <= NN) {
        int v = g_row_start[g] + g_chunk_sums[blockIdx.x];
        g_row_start[g] = v;
        if (g < NN) g_cursor[g] = v;
    }
}

__global__ void k_scatter_cols(const void* __restrict__ ei, long long E)
{
    long long e = (long long)blockIdx.x * blockDim.x + threadIdx.x;
    if (e >= E) return;
    int row = load_idx(ei, e);
    int col = load_idx(ei, E + e);
    if ((unsigned)row >= (unsigned)NN || (unsigned)col >= (unsigned)NN) return;
    int pos = atomicAdd(&g_cursor[row], 1);
    g_cols[pos] = col;
}

// ---------------------------------------------------------------------------
// accumulate: half-warp per row, float4 per lane, bias as init, plain store
// ---------------------------------------------------------------------------
__global__ void __launch_bounds__(256) k_accum(const float* __restrict__ b,
                                               float4* __restrict__ out4)
{
    const int lane = threadIdx.x & 31;
    const int warp = (blockIdx.x * blockDim.x + threadIdx.x) >> 5;
    const int row  = warp * 2 + (lane >> 4);
    const int sub  = lane & 15;
    if (row >= NN) return;

    const int beg = __ldg(&g_row_start[row]);
    const int end = __ldg(&g_row_start[row + 1]);

    const float4* Wt4 = (const float4*)g_Wt;
    float4 acc = __ldg(((const float4*)b) + sub);

    int i = beg;
    for (; i + 4 <= end; i += 4) {
        int c0 = __ldg(g_cols + i);
        int c1 = __ldg(g_cols + i + 1);
        int c2 = __ldg(g_cols + i + 2);
        int c3 = __ldg(g_cols + i + 3);
        float4 v0 = __ldg(Wt4 + (size_t)c0 * OC4 + sub);
        float4 v1 = __ldg(Wt4 + (size_t)c1 * OC4 + sub);
        float4 v2 = __ldg(Wt4 + (size_t)c2 * OC4 + sub);
        float4 v3 = __ldg(Wt4 + (size_t)c3 * OC4 + sub);
        acc.x += v0.x; acc.y += v0.y; acc.z += v0.z; acc.w += v0.w;
        acc.x += v1.x; acc.y += v1.y; acc.z += v1.z; acc.w += v1.w;
        acc.x += v2.x; acc.y += v2.y; acc.z += v2.z; acc.w += v2.w;
        acc.x += v3.x; acc.y += v3.y; acc.z += v3.z; acc.w += v3.w;
    }
    for (; i < end; ++i) {
        int c = __ldg(g_cols + i);
        float4 v = __ldg(Wt4 + (size_t)c * OC4 + sub);
        acc.x += v.x; acc.y += v.y; acc.z += v.z; acc.w += v.w;
    }
    out4[(size_t)row * OC4 + sub] = acc;
}

// ---------------------------------------------------------------------------
extern "C" void kernel_launch(void* const* d_in, const int* in_sizes, int n_in,
                              void* d_out, int out_size)
{
    const void*  ei  = d_in[0];                  // [2,E] int32 or int64
    const float* W   = (const float*)d_in[1];    // [64,N]
    const float* b   = (const float*)d_in[2];    // [64]
    float4*      out = (float4*)d_out;           // [N,64]

    const long long E = (long long)in_sizes[0] / 2;
    const int       n = in_sizes[1] / OC;        // = NN

    k_detect<<<1, 1>>>((const unsigned int*)ei);

    {   dim3 blk(32, 8), grd((n + 31) / 32);
        k_transpose<<<grd, blk>>>(W, n); }

    k_zero_counts<<<(NN + 256) / 256, 256>>>();

    {   int thr = 256;
        long long blocks = (E + thr - 1) / thr;
        k_hist<<<(unsigned)blocks, thr>>>(ei, E);
        k_scan1<<<NCHUNK, SCAN_CHUNK>>>();
        k_scan2<<<1, 1>>>();
        k_scan3<<<NCHUNK, SCAN_CHUNK>>>();
        k_scatter_cols<<<(unsigned)blocks, thr>>>(ei, E);
    }

    {   // 2 rows per warp, 8 warps per block -> 16 rows/block
        int rows_per_block = 16;
        int blocks = (NN + rows_per_block - 1) / rows_per_block;
        k_accum<<<blocks, 256>>>(b, out);
    }
}